// round 10
// baseline (speedup 1.0000x reference)
#include <cuda_runtime.h>
#include <cuda_bf16.h>
#include <cstdint>

// Live computation (GNN branch is dead code in the reference):
//   h1 = relu(sf @ Wfc1^T + bfc1)     [N,12] -> [N,64]   (HMMA, K padded to 16)
//   h2 = relu(h1 @ Wfc2^T + bfc2)     [N,64] -> [N,64]   (HMMA, A register-chained)
//   out = h2 @ Wp^T + bp              [N,64] -> [N,1]    (register epilogue)
//
// Round 10: persistent single-wave version of R9. grid = 296 (exactly 2 CTAs/SM
// on 148 SMs), each block loops over <=3 node-tiles; weights staged once; next
// tile's sf loads prefetched under the current tile's MMAs. Tile loop is
// sync-free (smem read-only after the one __syncthreads).

#define NN     100000
#define SF     12
#define FC     64
#define TPB    256
#define NPB    128
#define GRID   296
#define NTMAX  3              // ceil(782 / 296)
#define BSTR   144            // W2 smem row stride (bytes): 9x16B, conflict-free
#define WSTR   48             // W1 smem row stride (bytes): 3x16B, conflict-free

// ---- dynamic smem layout (byte offsets) ----
#define OFF_B2H  0            // 64 x 144
#define OFF_B2L  9216         // 64 x 144
#define OFF_W1H  18432        // 64 x 48
#define OFF_W1L  21504        // 64 x 48
#define OFF_B1   24576        // float[64]
#define OFF_B2   24832        // float[64]
#define OFF_WP   25088        // float[64]
#define OFF_BP   25344        // float
#define SMEM_DYN 25600

__device__ __forceinline__ uint32_t smem_u32(const void* p) {
    uint32_t a;
    asm("{ .reg .u64 t; cvta.to.shared.u64 t, %1; cvt.u32.u64 %0, t; }"
        : "=r"(a) : "l"(p));
    return a;
}
// pack: f0 -> low bf16, f1 -> high bf16
__device__ __forceinline__ uint32_t bf16x2_of(float f0, float f1) {
    uint32_t r;
    asm("cvt.rn.bf16x2.f32 %0, %1, %2;" : "=r"(r) : "f"(f1), "f"(f0));
    return r;
}
__device__ __forceinline__ void split2(float f0, float f1, uint32_t& h, uint32_t& l) {
    h = bf16x2_of(f0, f1);
    float g0 = __uint_as_float(h << 16);
    float g1 = __uint_as_float(h & 0xffff0000u);
    l = bf16x2_of(f0 - g0, f1 - g1);
}
__device__ __forceinline__ void ldsm_x4(uint32_t* r, uint32_t addr) {
    asm volatile("ldmatrix.sync.aligned.m8n8.x4.shared.b16 {%0,%1,%2,%3}, [%4];"
                 : "=r"(r[0]), "=r"(r[1]), "=r"(r[2]), "=r"(r[3]) : "r"(addr));
}
__device__ __forceinline__ void mma_bf16(float* d, const uint32_t* a, const uint32_t* b) {
    asm volatile(
        "mma.sync.aligned.m16n8k16.row.col.f32.bf16.bf16.f32 "
        "{%0,%1,%2,%3}, {%4,%5,%6,%7}, {%8,%9}, {%0,%1,%2,%3};"
        : "+f"(d[0]), "+f"(d[1]), "+f"(d[2]), "+f"(d[3])
        : "r"(a[0]), "r"(a[1]), "r"(a[2]), "r"(a[3]), "r"(b[0]), "r"(b[1]));
}

__global__ __launch_bounds__(TPB, 2)
void fused_mlp_hmma5(const float* __restrict__ sf,
                     const float* __restrict__ W1, const float* __restrict__ b1,
                     const float* __restrict__ W2, const float* __restrict__ b2,
                     const float* __restrict__ Wp, const float* __restrict__ bp,
                     float* __restrict__ out)
{
    extern __shared__ __align__(16) char base[];
    const uint32_t sb = smem_u32(base);

    const int tid  = threadIdx.x;
    const int lane = tid & 31;
    const int w    = tid >> 5;          // 0..7
    const int q    = lane & 3;
    const int r4   = lane >> 2;

    // ---- stage W2 -> B2h/B2l (rows = output j, 64 bf16 k-contig, stride 144) ----
    {
        const int row = tid >> 2, quarter = tid & 3;   // 16 floats per thread
        const float* src = W2 + row * FC + quarter * 16;
        #pragma unroll
        for (int g = 0; g < 2; g++) {
            float4 v0 = *(const float4*)(src + g * 8);
            float4 v1 = *(const float4*)(src + g * 8 + 4);
            uint32_t h0, l0, h1_, l1_, h2, l2, h3, l3;
            split2(v0.x, v0.y, h0, l0);
            split2(v0.z, v0.w, h1_, l1_);
            split2(v1.x, v1.y, h2, l2);
            split2(v1.z, v1.w, h3, l3);
            const int off = row * BSTR + quarter * 32 + g * 16;
            *(uint4*)(base + OFF_B2H + off) = make_uint4(h0, h1_, h2, h3);
            *(uint4*)(base + OFF_B2L + off) = make_uint4(l0, l1_, l2, l3);
        }
    }
    // ---- stage W1 -> W1h/W1l (12 bf16 + 4 zero pad per row, stride 48) ----
    if (tid < FC) {
        const float* src = W1 + tid * SF;
        float4 v0 = *(const float4*)(src);
        float4 v1 = *(const float4*)(src + 4);
        float4 v2 = *(const float4*)(src + 8);
        uint32_t h0, l0, h1_, l1_, h2, l2, h3, l3, h4, l4, h5, l5;
        split2(v0.x, v0.y, h0, l0);
        split2(v0.z, v0.w, h1_, l1_);
        split2(v1.x, v1.y, h2, l2);
        split2(v1.z, v1.w, h3, l3);
        split2(v2.x, v2.y, h4, l4);
        split2(v2.z, v2.w, h5, l5);
        const int off = tid * WSTR;
        *(uint4*)(base + OFF_W1H + off)      = make_uint4(h0, h1_, h2, h3);
        *(uint4*)(base + OFF_W1H + off + 16) = make_uint4(h4, h5, 0u, 0u);
        *(uint4*)(base + OFF_W1L + off)      = make_uint4(l0, l1_, l2, l3);
        *(uint4*)(base + OFF_W1L + off + 16) = make_uint4(l4, l5, 0u, 0u);
        ((float*)(base + OFF_B1))[tid] = b1[tid];
        ((float*)(base + OFF_B2))[tid] = b2[tid];
        ((float*)(base + OFF_WP))[tid] = Wp[tid];
    }
    if (tid == 0) *((float*)(base + OFF_BP)) = bp[0];

    const int local = lane & 7, mat = lane >> 3;
    const int kc = mat & 1, ntoff = mat >> 1;

    // ---- prefetch tile 0's sf values ----
    float2 v00 = make_float2(0.f, 0.f), v01 = v00, v10 = v00, v11 = v00;
    {
        const int mb = blockIdx.x * NPB + w * 16;
        const int row0 = mb + r4, row1 = row0 + 8;
        if (row0 < NN) {
            v00 = *(const float2*)(sf + (size_t)row0 * SF + 2 * q);
            if (q < 2) v01 = *(const float2*)(sf + (size_t)row0 * SF + 2 * q + 8);
        }
        if (row1 < NN) {
            v10 = *(const float2*)(sf + (size_t)row1 * SF + 2 * q);
            if (q < 2) v11 = *(const float2*)(sf + (size_t)row1 * SF + 2 * q + 8);
        }
    }
    __syncthreads();   // smem staged; read-only from here (loop is sync-free)

    const float bps = *((const float*)(base + OFF_BP));

    for (int t = 0; t < NTMAX; t++) {
        const int tile = blockIdx.x + t * GRID;
        if (tile * NPB >= NN) break;
        const int mbase = tile * NPB + w * 16;

        // ---- layer-1 A fragments from prefetched values ----
        uint32_t Ah1[4], Al1[4];
        split2(v00.x, v00.y, Ah1[0], Al1[0]);
        split2(v10.x, v10.y, Ah1[1], Al1[1]);
        split2(v01.x, v01.y, Ah1[2], Al1[2]);
        split2(v11.x, v11.y, Ah1[3], Al1[3]);

        // ---- prefetch next tile's sf (overlaps with both MMA phases) ----
        v00 = make_float2(0.f, 0.f); v01 = v00; v10 = v00; v11 = v00;
        {
            const int ntile = tile + GRID;
            if (t + 1 < NTMAX && ntile * NPB < NN) {
                const int mb = ntile * NPB + w * 16;
                const int row0 = mb + r4, row1 = row0 + 8;
                if (row0 < NN) {
                    v00 = *(const float2*)(sf + (size_t)row0 * SF + 2 * q);
                    if (q < 2) v01 = *(const float2*)(sf + (size_t)row0 * SF + 2 * q + 8);
                }
                if (row1 < NN) {
                    v10 = *(const float2*)(sf + (size_t)row1 * SF + 2 * q);
                    if (q < 2) v11 = *(const float2*)(sf + (size_t)row1 * SF + 2 * q + 8);
                }
            }
        }

        // ---- layer-1 MMA: D1[8][4], term-major (8 independent chains) ----
        float D1[8][4];
        {
            uint32_t B1h[8][2], B1l[8][2];
            #pragma unroll
            for (int p = 0; p < 4; p++) {
                const uint32_t roff = ((2 * p + ntoff) * 8 + local) * WSTR + kc * 16;
                uint32_t r[4];
                ldsm_x4(r, sb + OFF_W1H + roff);
                B1h[2 * p][0] = r[0]; B1h[2 * p][1] = r[1];
                B1h[2 * p + 1][0] = r[2]; B1h[2 * p + 1][1] = r[3];
                ldsm_x4(r, sb + OFF_W1L + roff);
                B1l[2 * p][0] = r[0]; B1l[2 * p][1] = r[1];
                B1l[2 * p + 1][0] = r[2]; B1l[2 * p + 1][1] = r[3];
            }
            #pragma unroll
            for (int n = 0; n < 8; n++) {
                #pragma unroll
                for (int c = 0; c < 4; c++) D1[n][c] = 0.0f;
            }
            #pragma unroll
            for (int n = 0; n < 8; n++) mma_bf16(D1[n], Ah1, B1h[n]);
            #pragma unroll
            for (int n = 0; n < 8; n++) mma_bf16(D1[n], Al1, B1h[n]);
            #pragma unroll
            for (int n = 0; n < 8; n++) mma_bf16(D1[n], Ah1, B1l[n]);
        }

        // ---- epilogue-1: relu + b1; layer-2 A fragments (register chain) ----
        uint32_t A2h[4][4], A2l[4][4];
        {
            #pragma unroll
            for (int n = 0; n < 8; n++) {
                const float2 bv = *(const float2*)(base + OFF_B1 + (n * 8 + 2 * q) * 4);
                D1[n][0] = fmaxf(D1[n][0] + bv.x, 0.0f);
                D1[n][1] = fmaxf(D1[n][1] + bv.y, 0.0f);
                D1[n][2] = fmaxf(D1[n][2] + bv.x, 0.0f);
                D1[n][3] = fmaxf(D1[n][3] + bv.y, 0.0f);
            }
            #pragma unroll
            for (int kt = 0; kt < 4; kt++) {
                split2(D1[2 * kt][0],     D1[2 * kt][1],     A2h[kt][0], A2l[kt][0]);
                split2(D1[2 * kt][2],     D1[2 * kt][3],     A2h[kt][1], A2l[kt][1]);
                split2(D1[2 * kt + 1][0], D1[2 * kt + 1][1], A2h[kt][2], A2l[kt][2]);
                split2(D1[2 * kt + 1][2], D1[2 * kt + 1][3], A2h[kt][3], A2l[kt][3]);
            }
        }

        // ---- layer-2 MMA: D2 = A2h*B2h + A2l*B2h + A2h*B2l, term-major per kt ----
        float D2[8][4];
        #pragma unroll
        for (int n = 0; n < 8; n++)
            #pragma unroll
            for (int c = 0; c < 4; c++) D2[n][c] = 0.0f;

        #pragma unroll
        for (int kt = 0; kt < 4; kt++) {
            uint32_t bh[4][4], bl[4][4];
            #pragma unroll
            for (int p = 0; p < 4; p++) {
                const uint32_t roff = ((2 * p + ntoff) * 8 + local) * BSTR + kt * 32 + kc * 16;
                ldsm_x4(bh[p], sb + OFF_B2H + roff);
                ldsm_x4(bl[p], sb + OFF_B2L + roff);
            }
            #pragma unroll
            for (int p = 0; p < 4; p++) {
                mma_bf16(D2[2 * p],     A2h[kt], &bh[p][0]);
                mma_bf16(D2[2 * p + 1], A2h[kt], &bh[p][2]);
            }
            #pragma unroll
            for (int p = 0; p < 4; p++) {
                mma_bf16(D2[2 * p],     A2l[kt], &bh[p][0]);
                mma_bf16(D2[2 * p + 1], A2l[kt], &bh[p][2]);
            }
            #pragma unroll
            for (int p = 0; p < 4; p++) {
                mma_bf16(D2[2 * p],     A2h[kt], &bl[p][0]);
                mma_bf16(D2[2 * p + 1], A2h[kt], &bl[p][2]);
            }
        }

        // ---- epilogue-2: relu + b2, dot with Wp, quad-reduce, store ----
        {
            float p0 = 0.0f, p1 = 0.0f;
            #pragma unroll
            for (int n = 0; n < 8; n++) {
                const float2 g  = *(const float2*)(base + OFF_B2 + (n * 8 + 2 * q) * 4);
                const float2 wv = *(const float2*)(base + OFF_WP + (n * 8 + 2 * q) * 4);
                p0 = fmaf(wv.x, fmaxf(D2[n][0] + g.x, 0.0f), p0);
                p0 = fmaf(wv.y, fmaxf(D2[n][1] + g.y, 0.0f), p0);
                p1 = fmaf(wv.x, fmaxf(D2[n][2] + g.x, 0.0f), p1);
                p1 = fmaf(wv.y, fmaxf(D2[n][3] + g.y, 0.0f), p1);
            }
            p0 += __shfl_xor_sync(0xffffffffu, p0, 1);
            p0 += __shfl_xor_sync(0xffffffffu, p0, 2);
            p1 += __shfl_xor_sync(0xffffffffu, p1, 1);
            p1 += __shfl_xor_sync(0xffffffffu, p1, 2);
            if (q == 0) {
                const int n0 = mbase + r4;
                if (n0 < NN)     out[n0]     = p0 + bps;
                if (n0 + 8 < NN) out[n0 + 8] = p1 + bps;
            }
        }
    }
}

extern "C" void kernel_launch(void* const* d_in, const int* in_sizes, int n_in,
                              void* d_out, int out_size)
{
    const float* sf = (const float*)d_in[2];
    const float* W1 = (const float*)d_in[9];
    const float* b1 = (const float*)d_in[10];
    const float* W2 = (const float*)d_in[11];
    const float* b2 = (const float*)d_in[12];
    const float* Wp = (const float*)d_in[13];
    const float* bp = (const float*)d_in[14];
    float* out = (float*)d_out;

    cudaFuncSetAttribute(fused_mlp_hmma5,
                         cudaFuncAttributeMaxDynamicSharedMemorySize, SMEM_DYN);
    fused_mlp_hmma5<<<GRID, TPB, SMEM_DYN>>>(sf, W1, b1, W2, b2, Wp, bp, out);
}

// round 11
// speedup vs baseline: 1.2249x; 1.2249x over previous
#include <cuda_runtime.h>
#include <cuda_fp16.h>
#include <cstdint>

// Live computation (GNN branch is dead code in the reference):
//   h1 = relu(sf @ Wfc1^T + bfc1)     [N,12] -> [N,64]   (HMMA fp16, K padded to 16)
//   h2 = relu(h1 @ Wfc2^T + bfc2)     [N,64] -> [N,64]   (HMMA fp16, A register-chained)
//   out = h2 @ Wp^T + bp              [N,64] -> [N,1]    (register epilogue)
//
// Round 11: fp16 instead of bf16. fp16's 11-bit significand (half-ulp 2^-11)
// lets the ACTIVATION side go unsplit; only the weights are split (B = Bh+Bl,
// staged once per block). 2 MMA terms instead of 3 (80 vs 120 HMMA/warp/tile)
// and the serial epilogue-1 split chain collapses to 8 cvt.rn.f16x2.f32.
// Predicted rel_err ~1-4e-4 (fp32 accumulate, B-split exact to 2^-22).

#define NN     100000
#define SF     12
#define FC     64
#define TPB    256
#define NPB    128
#define GRID   296            // exactly 2 CTAs/SM on 148 SMs -> single wave
#define NTMAX  3              // ceil(782 / 296)
#define BSTR   144            // W2 smem row stride (bytes): 9x16B, conflict-free
#define WSTR   48             // W1 smem row stride (bytes): 3x16B, conflict-free

// ---- dynamic smem layout (byte offsets) ----
#define OFF_B2H  0            // 64 x 144
#define OFF_B2L  9216         // 64 x 144
#define OFF_W1H  18432        // 64 x 48
#define OFF_W1L  21504        // 64 x 48
#define OFF_B1   24576        // float[64]
#define OFF_B2   24832        // float[64]
#define OFF_WP   25088        // float[64]
#define OFF_BP   25344        // float
#define SMEM_DYN 25600

__device__ __forceinline__ uint32_t smem_u32(const void* p) {
    uint32_t a;
    asm("{ .reg .u64 t; cvta.to.shared.u64 t, %1; cvt.u32.u64 %0, t; }"
        : "=r"(a) : "l"(p));
    return a;
}
// pack: f0 -> low f16, f1 -> high f16
__device__ __forceinline__ uint32_t f16x2_of(float f0, float f1) {
    uint32_t r;
    asm("cvt.rn.f16x2.f32 %0, %1, %2;" : "=r"(r) : "f"(f1), "f"(f0));
    return r;
}
// weight split: w = hi(f16) + lo(f16), exact to ~2^-22
__device__ __forceinline__ void split2h(float f0, float f1, uint32_t& h, uint32_t& l) {
    h = f16x2_of(f0, f1);
    const __half2 hh = *reinterpret_cast<const __half2*>(&h);
    const float g0 = __low2float(hh);
    const float g1 = __high2float(hh);
    l = f16x2_of(f0 - g0, f1 - g1);
}
__device__ __forceinline__ void ldsm_x4(uint32_t* r, uint32_t addr) {
    asm volatile("ldmatrix.sync.aligned.m8n8.x4.shared.b16 {%0,%1,%2,%3}, [%4];"
                 : "=r"(r[0]), "=r"(r[1]), "=r"(r[2]), "=r"(r[3]) : "r"(addr));
}
__device__ __forceinline__ void mma_f16(float* d, const uint32_t* a, const uint32_t* b) {
    asm volatile(
        "mma.sync.aligned.m16n8k16.row.col.f32.f16.f16.f32 "
        "{%0,%1,%2,%3}, {%4,%5,%6,%7}, {%8,%9}, {%0,%1,%2,%3};"
        : "+f"(d[0]), "+f"(d[1]), "+f"(d[2]), "+f"(d[3])
        : "r"(a[0]), "r"(a[1]), "r"(a[2]), "r"(a[3]), "r"(b[0]), "r"(b[1]));
}

__global__ __launch_bounds__(TPB, 2)
void fused_mlp_hmma6(const float* __restrict__ sf,
                     const float* __restrict__ W1, const float* __restrict__ b1,
                     const float* __restrict__ W2, const float* __restrict__ b2,
                     const float* __restrict__ Wp, const float* __restrict__ bp,
                     float* __restrict__ out)
{
    extern __shared__ __align__(16) char base[];
    const uint32_t sb = smem_u32(base);

    const int tid  = threadIdx.x;
    const int lane = tid & 31;
    const int w    = tid >> 5;          // 0..7
    const int q    = lane & 3;
    const int r4   = lane >> 2;

    // ---- stage W2 -> B2h/B2l (rows = output j, 64 f16 k-contig, stride 144) ----
    {
        const int row = tid >> 2, quarter = tid & 3;   // 16 floats per thread
        const float* src = W2 + row * FC + quarter * 16;
        #pragma unroll
        for (int g = 0; g < 2; g++) {
            float4 v0 = *(const float4*)(src + g * 8);
            float4 v1 = *(const float4*)(src + g * 8 + 4);
            uint32_t h0, l0, h1_, l1_, h2, l2, h3, l3;
            split2h(v0.x, v0.y, h0, l0);
            split2h(v0.z, v0.w, h1_, l1_);
            split2h(v1.x, v1.y, h2, l2);
            split2h(v1.z, v1.w, h3, l3);
            const int off = row * BSTR + quarter * 32 + g * 16;
            *(uint4*)(base + OFF_B2H + off) = make_uint4(h0, h1_, h2, h3);
            *(uint4*)(base + OFF_B2L + off) = make_uint4(l0, l1_, l2, l3);
        }
    }
    // ---- stage W1 -> W1h/W1l (12 f16 + 4 zero pad per row, stride 48) ----
    if (tid < FC) {
        const float* src = W1 + tid * SF;
        float4 v0 = *(const float4*)(src);
        float4 v1 = *(const float4*)(src + 4);
        float4 v2 = *(const float4*)(src + 8);
        uint32_t h0, l0, h1_, l1_, h2, l2, h3, l3, h4, l4, h5, l5;
        split2h(v0.x, v0.y, h0, l0);
        split2h(v0.z, v0.w, h1_, l1_);
        split2h(v1.x, v1.y, h2, l2);
        split2h(v1.z, v1.w, h3, l3);
        split2h(v2.x, v2.y, h4, l4);
        split2h(v2.z, v2.w, h5, l5);
        const int off = tid * WSTR;
        *(uint4*)(base + OFF_W1H + off)      = make_uint4(h0, h1_, h2, h3);
        *(uint4*)(base + OFF_W1H + off + 16) = make_uint4(h4, h5, 0u, 0u);
        *(uint4*)(base + OFF_W1L + off)      = make_uint4(l0, l1_, l2, l3);
        *(uint4*)(base + OFF_W1L + off + 16) = make_uint4(l4, l5, 0u, 0u);
        ((float*)(base + OFF_B1))[tid] = b1[tid];
        ((float*)(base + OFF_B2))[tid] = b2[tid];
        ((float*)(base + OFF_WP))[tid] = Wp[tid];
    }
    if (tid == 0) *((float*)(base + OFF_BP)) = bp[0];

    const int local = lane & 7, mat = lane >> 3;
    const int kc = mat & 1, ntoff = mat >> 1;

    // ---- prefetch tile 0's sf values ----
    float2 v00 = make_float2(0.f, 0.f), v01 = v00, v10 = v00, v11 = v00;
    {
        const int mb = blockIdx.x * NPB + w * 16;
        const int row0 = mb + r4, row1 = row0 + 8;
        if (row0 < NN) {
            v00 = *(const float2*)(sf + (size_t)row0 * SF + 2 * q);
            if (q < 2) v01 = *(const float2*)(sf + (size_t)row0 * SF + 2 * q + 8);
        }
        if (row1 < NN) {
            v10 = *(const float2*)(sf + (size_t)row1 * SF + 2 * q);
            if (q < 2) v11 = *(const float2*)(sf + (size_t)row1 * SF + 2 * q + 8);
        }
    }
    __syncthreads();   // smem staged; read-only from here (loop is sync-free)

    const float bps = *((const float*)(base + OFF_BP));

    for (int t = 0; t < NTMAX; t++) {
        const int tile = blockIdx.x + t * GRID;
        if (tile * NPB >= NN) break;
        const int mbase = tile * NPB + w * 16;

        // ---- layer-1 A fragments: plain fp16, no split ----
        uint32_t A1[4];
        A1[0] = f16x2_of(v00.x, v00.y);
        A1[1] = f16x2_of(v10.x, v10.y);
        A1[2] = f16x2_of(v01.x, v01.y);
        A1[3] = f16x2_of(v11.x, v11.y);

        // ---- prefetch next tile's sf (overlaps with both MMA phases) ----
        v00 = make_float2(0.f, 0.f); v01 = v00; v10 = v00; v11 = v00;
        {
            const int ntile = tile + GRID;
            if (t + 1 < NTMAX && ntile * NPB < NN) {
                const int mb = ntile * NPB + w * 16;
                const int row0 = mb + r4, row1 = row0 + 8;
                if (row0 < NN) {
                    v00 = *(const float2*)(sf + (size_t)row0 * SF + 2 * q);
                    if (q < 2) v01 = *(const float2*)(sf + (size_t)row0 * SF + 2 * q + 8);
                }
                if (row1 < NN) {
                    v10 = *(const float2*)(sf + (size_t)row1 * SF + 2 * q);
                    if (q < 2) v11 = *(const float2*)(sf + (size_t)row1 * SF + 2 * q + 8);
                }
            }
        }

        // ---- layer-1 MMA: D1 = A1*B1h + A1*B1l, term-major (8 chains) ----
        float D1[8][4];
        {
            uint32_t B1h[8][2], B1l[8][2];
            #pragma unroll
            for (int p = 0; p < 4; p++) {
                const uint32_t roff = ((2 * p + ntoff) * 8 + local) * WSTR + kc * 16;
                uint32_t r[4];
                ldsm_x4(r, sb + OFF_W1H + roff);
                B1h[2 * p][0] = r[0]; B1h[2 * p][1] = r[1];
                B1h[2 * p + 1][0] = r[2]; B1h[2 * p + 1][1] = r[3];
                ldsm_x4(r, sb + OFF_W1L + roff);
                B1l[2 * p][0] = r[0]; B1l[2 * p][1] = r[1];
                B1l[2 * p + 1][0] = r[2]; B1l[2 * p + 1][1] = r[3];
            }
            #pragma unroll
            for (int n = 0; n < 8; n++) {
                #pragma unroll
                for (int c = 0; c < 4; c++) D1[n][c] = 0.0f;
            }
            #pragma unroll
            for (int n = 0; n < 8; n++) mma_f16(D1[n], A1, B1h[n]);
            #pragma unroll
            for (int n = 0; n < 8; n++) mma_f16(D1[n], A1, B1l[n]);
        }

        // ---- epilogue-1: relu + b1; pack h1 to fp16 A2 fragments (no split) ----
        // k-tile kt of layer-2 A == D1 n-tiles {2kt, 2kt+1}.
        uint32_t A2[4][4];
        {
            #pragma unroll
            for (int n = 0; n < 8; n++) {
                const float2 bv = *(const float2*)(base + OFF_B1 + (n * 8 + 2 * q) * 4);
                D1[n][0] = fmaxf(D1[n][0] + bv.x, 0.0f);
                D1[n][1] = fmaxf(D1[n][1] + bv.y, 0.0f);
                D1[n][2] = fmaxf(D1[n][2] + bv.x, 0.0f);
                D1[n][3] = fmaxf(D1[n][3] + bv.y, 0.0f);
            }
            #pragma unroll
            for (int kt = 0; kt < 4; kt++) {
                A2[kt][0] = f16x2_of(D1[2 * kt][0],     D1[2 * kt][1]);
                A2[kt][1] = f16x2_of(D1[2 * kt][2],     D1[2 * kt][3]);
                A2[kt][2] = f16x2_of(D1[2 * kt + 1][0], D1[2 * kt + 1][1]);
                A2[kt][3] = f16x2_of(D1[2 * kt + 1][2], D1[2 * kt + 1][3]);
            }
        }

        // ---- layer-2 MMA: D2 = A2*B2h + A2*B2l, term-major per kt ----
        float D2[8][4];
        #pragma unroll
        for (int n = 0; n < 8; n++)
            #pragma unroll
            for (int c = 0; c < 4; c++) D2[n][c] = 0.0f;

        #pragma unroll
        for (int kt = 0; kt < 4; kt++) {
            uint32_t bh[4][4], bl[4][4];
            #pragma unroll
            for (int p = 0; p < 4; p++) {
                const uint32_t roff = ((2 * p + ntoff) * 8 + local) * BSTR + kt * 32 + kc * 16;
                ldsm_x4(bh[p], sb + OFF_B2H + roff);
                ldsm_x4(bl[p], sb + OFF_B2L + roff);
            }
            #pragma unroll
            for (int p = 0; p < 4; p++) {
                mma_f16(D2[2 * p],     A2[kt], &bh[p][0]);
                mma_f16(D2[2 * p + 1], A2[kt], &bh[p][2]);
            }
            #pragma unroll
            for (int p = 0; p < 4; p++) {
                mma_f16(D2[2 * p],     A2[kt], &bl[p][0]);
                mma_f16(D2[2 * p + 1], A2[kt], &bl[p][2]);
            }
        }

        // ---- epilogue-2: relu + b2, dot with Wp, quad-reduce, store ----
        {
            float p0 = 0.0f, p1 = 0.0f;
            #pragma unroll
            for (int n = 0; n < 8; n++) {
                const float2 g  = *(const float2*)(base + OFF_B2 + (n * 8 + 2 * q) * 4);
                const float2 wv = *(const float2*)(base + OFF_WP + (n * 8 + 2 * q) * 4);
                p0 = fmaf(wv.x, fmaxf(D2[n][0] + g.x, 0.0f), p0);
                p0 = fmaf(wv.y, fmaxf(D2[n][1] + g.y, 0.0f), p0);
                p1 = fmaf(wv.x, fmaxf(D2[n][2] + g.x, 0.0f), p1);
                p1 = fmaf(wv.y, fmaxf(D2[n][3] + g.y, 0.0f), p1);
            }
            p0 += __shfl_xor_sync(0xffffffffu, p0, 1);
            p0 += __shfl_xor_sync(0xffffffffu, p0, 2);
            p1 += __shfl_xor_sync(0xffffffffu, p1, 1);
            p1 += __shfl_xor_sync(0xffffffffu, p1, 2);
            if (q == 0) {
                const int n0 = mbase + r4;
                if (n0 < NN)     out[n0]     = p0 + bps;
                if (n0 + 8 < NN) out[n0 + 8] = p1 + bps;
            }
        }
    }
}

extern "C" void kernel_launch(void* const* d_in, const int* in_sizes, int n_in,
                              void* d_out, int out_size)
{
    const float* sf = (const float*)d_in[2];
    const float* W1 = (const float*)d_in[9];
    const float* b1 = (const float*)d_in[10];
    const float* W2 = (const float*)d_in[11];
    const float* b2 = (const float*)d_in[12];
    const float* Wp = (const float*)d_in[13];
    const float* bp = (const float*)d_in[14];
    float* out = (float*)d_out;

    cudaFuncSetAttribute(fused_mlp_hmma6,
                         cudaFuncAttributeMaxDynamicSharedMemorySize, SMEM_DYN);
    fused_mlp_hmma6<<<GRID, TPB, SMEM_DYN>>>(sf, W1, b1, W2, b2, Wp, bp, out);
}

// round 12
// speedup vs baseline: 1.5607x; 1.2741x over previous
#include <cuda_runtime.h>
#include <cuda_fp16.h>
#include <cstdint>

// Live computation (GNN branch is dead code in the reference):
//   h1 = relu(sf @ Wfc1^T + bfc1)     [N,12] -> [N,64]   (HMMA fp16, K padded to 16)
//   h2 = relu(h1 @ Wfc2^T + bfc2)     [N,64] -> [N,64]   (HMMA fp16, A register-chained)
//   out = h2 @ Wp^T + bp              [N,64] -> [N,1]    (register epilogue)
//
// Round 12: fully unsplit fp16 (activations AND weights plain fp16, fp32
// accumulate). Measured rel_err with unsplit-A was 3.5e-5; weight rounding
// adds ~2-4e-4 total — still several x under the 1e-3 threshold.
// 40 HMMA + 12 ldsm per warp per tile (half of round 11).

#define NN     100000
#define SF     12
#define FC     64
#define TPB    256
#define NPB    128
#define GRID   296            // exactly 2 CTAs/SM on 148 SMs -> single wave
#define NTMAX  3              // ceil(782 / 296)
#define BSTR   144            // W2 smem row stride (bytes): 9x16B, conflict-free
#define WSTR   48             // W1 smem row stride (bytes): 3x16B, conflict-free

// ---- dynamic smem layout (byte offsets) ----
#define OFF_B2H  0            // 64 x 144 (W2 as f16)
#define OFF_W1H  9216         // 64 x 48  (W1 as f16, K padded to 16)
#define OFF_B1   12288        // float[64]
#define OFF_B2   12544        // float[64]
#define OFF_WP   12800        // float[64]
#define OFF_BP   13056        // float
#define SMEM_DYN 13312

__device__ __forceinline__ uint32_t smem_u32(const void* p) {
    uint32_t a;
    asm("{ .reg .u64 t; cvta.to.shared.u64 t, %1; cvt.u32.u64 %0, t; }"
        : "=r"(a) : "l"(p));
    return a;
}
// pack: f0 -> low f16, f1 -> high f16
__device__ __forceinline__ uint32_t f16x2_of(float f0, float f1) {
    uint32_t r;
    asm("cvt.rn.f16x2.f32 %0, %1, %2;" : "=r"(r) : "f"(f1), "f"(f0));
    return r;
}
__device__ __forceinline__ void ldsm_x4(uint32_t* r, uint32_t addr) {
    asm volatile("ldmatrix.sync.aligned.m8n8.x4.shared.b16 {%0,%1,%2,%3}, [%4];"
                 : "=r"(r[0]), "=r"(r[1]), "=r"(r[2]), "=r"(r[3]) : "r"(addr));
}
__device__ __forceinline__ void mma_f16(float* d, const uint32_t* a, const uint32_t* b) {
    asm volatile(
        "mma.sync.aligned.m16n8k16.row.col.f32.f16.f16.f32 "
        "{%0,%1,%2,%3}, {%4,%5,%6,%7}, {%8,%9}, {%0,%1,%2,%3};"
        : "+f"(d[0]), "+f"(d[1]), "+f"(d[2]), "+f"(d[3])
        : "r"(a[0]), "r"(a[1]), "r"(a[2]), "r"(a[3]), "r"(b[0]), "r"(b[1]));
}

__global__ __launch_bounds__(TPB, 2)
void fused_mlp_hmma7(const float* __restrict__ sf,
                     const float* __restrict__ W1, const float* __restrict__ b1,
                     const float* __restrict__ W2, const float* __restrict__ b2,
                     const float* __restrict__ Wp, const float* __restrict__ bp,
                     float* __restrict__ out)
{
    extern __shared__ __align__(16) char base[];
    const uint32_t sb = smem_u32(base);

    const int tid  = threadIdx.x;
    const int lane = tid & 31;
    const int w    = tid >> 5;          // 0..7
    const int q    = lane & 3;
    const int r4   = lane >> 2;

    // ---- stage W2 -> f16 rows (row j = 64 f16 k-contig, stride 144) ----
    {
        const int row = tid >> 2, quarter = tid & 3;   // 16 floats per thread
        const float* src = W2 + row * FC + quarter * 16;
        #pragma unroll
        for (int g = 0; g < 2; g++) {
            float4 v0 = *(const float4*)(src + g * 8);
            float4 v1 = *(const float4*)(src + g * 8 + 4);
            const int off = row * BSTR + quarter * 32 + g * 16;
            *(uint4*)(base + OFF_B2H + off) =
                make_uint4(f16x2_of(v0.x, v0.y), f16x2_of(v0.z, v0.w),
                           f16x2_of(v1.x, v1.y), f16x2_of(v1.z, v1.w));
        }
    }
    // ---- stage W1 -> f16 rows (12 f16 + 4 zero pad per row, stride 48) ----
    if (tid < FC) {
        const float* src = W1 + tid * SF;
        float4 v0 = *(const float4*)(src);
        float4 v1 = *(const float4*)(src + 4);
        float4 v2 = *(const float4*)(src + 8);
        const int off = tid * WSTR;
        *(uint4*)(base + OFF_W1H + off) =
            make_uint4(f16x2_of(v0.x, v0.y), f16x2_of(v0.z, v0.w),
                       f16x2_of(v1.x, v1.y), f16x2_of(v1.z, v1.w));
        *(uint4*)(base + OFF_W1H + off + 16) =
            make_uint4(f16x2_of(v2.x, v2.y), f16x2_of(v2.z, v2.w), 0u, 0u);
        ((float*)(base + OFF_B1))[tid] = b1[tid];
        ((float*)(base + OFF_B2))[tid] = b2[tid];
        ((float*)(base + OFF_WP))[tid] = Wp[tid];
    }
    if (tid == 0) *((float*)(base + OFF_BP)) = bp[0];

    const int local = lane & 7, mat = lane >> 3;
    const int kc = mat & 1, ntoff = mat >> 1;

    // ---- prefetch tile 0's sf values ----
    float2 v00 = make_float2(0.f, 0.f), v01 = v00, v10 = v00, v11 = v00;
    {
        const int mb = blockIdx.x * NPB + w * 16;
        const int row0 = mb + r4, row1 = row0 + 8;
        if (row0 < NN) {
            v00 = *(const float2*)(sf + (size_t)row0 * SF + 2 * q);
            if (q < 2) v01 = *(const float2*)(sf + (size_t)row0 * SF + 2 * q + 8);
        }
        if (row1 < NN) {
            v10 = *(const float2*)(sf + (size_t)row1 * SF + 2 * q);
            if (q < 2) v11 = *(const float2*)(sf + (size_t)row1 * SF + 2 * q + 8);
        }
    }
    __syncthreads();   // smem staged; read-only from here (loop is sync-free)

    const float bps = *((const float*)(base + OFF_BP));

    for (int t = 0; t < NTMAX; t++) {
        const int tile = blockIdx.x + t * GRID;
        if (tile * NPB >= NN) break;
        const int mbase = tile * NPB + w * 16;

        // ---- layer-1 A fragments: plain fp16 ----
        uint32_t A1[4];
        A1[0] = f16x2_of(v00.x, v00.y);
        A1[1] = f16x2_of(v10.x, v10.y);
        A1[2] = f16x2_of(v01.x, v01.y);
        A1[3] = f16x2_of(v11.x, v11.y);

        // ---- prefetch next tile's sf (overlaps with both MMA phases) ----
        v00 = make_float2(0.f, 0.f); v01 = v00; v10 = v00; v11 = v00;
        {
            const int ntile = tile + GRID;
            if (t + 1 < NTMAX && ntile * NPB < NN) {
                const int mb = ntile * NPB + w * 16;
                const int row0 = mb + r4, row1 = row0 + 8;
                if (row0 < NN) {
                    v00 = *(const float2*)(sf + (size_t)row0 * SF + 2 * q);
                    if (q < 2) v01 = *(const float2*)(sf + (size_t)row0 * SF + 2 * q + 8);
                }
                if (row1 < NN) {
                    v10 = *(const float2*)(sf + (size_t)row1 * SF + 2 * q);
                    if (q < 2) v11 = *(const float2*)(sf + (size_t)row1 * SF + 2 * q + 8);
                }
            }
        }

        // ---- layer-1 MMA: 8 independent chains ----
        float D1[8][4];
        {
            uint32_t B1h[8][2];
            #pragma unroll
            for (int p = 0; p < 4; p++) {
                const uint32_t roff = ((2 * p + ntoff) * 8 + local) * WSTR + kc * 16;
                uint32_t r[4];
                ldsm_x4(r, sb + OFF_W1H + roff);
                B1h[2 * p][0] = r[0]; B1h[2 * p][1] = r[1];
                B1h[2 * p + 1][0] = r[2]; B1h[2 * p + 1][1] = r[3];
            }
            #pragma unroll
            for (int n = 0; n < 8; n++) {
                #pragma unroll
                for (int c = 0; c < 4; c++) D1[n][c] = 0.0f;
            }
            #pragma unroll
            for (int n = 0; n < 8; n++) mma_f16(D1[n], A1, B1h[n]);
        }

        // ---- epilogue-1: relu + b1; pack h1 to fp16 A2 fragments ----
        // k-tile kt of layer-2 A == D1 n-tiles {2kt, 2kt+1}.
        uint32_t A2[4][4];
        {
            #pragma unroll
            for (int n = 0; n < 8; n++) {
                const float2 bv = *(const float2*)(base + OFF_B1 + (n * 8 + 2 * q) * 4);
                D1[n][0] = fmaxf(D1[n][0] + bv.x, 0.0f);
                D1[n][1] = fmaxf(D1[n][1] + bv.y, 0.0f);
                D1[n][2] = fmaxf(D1[n][2] + bv.x, 0.0f);
                D1[n][3] = fmaxf(D1[n][3] + bv.y, 0.0f);
            }
            #pragma unroll
            for (int kt = 0; kt < 4; kt++) {
                A2[kt][0] = f16x2_of(D1[2 * kt][0],     D1[2 * kt][1]);
                A2[kt][1] = f16x2_of(D1[2 * kt][2],     D1[2 * kt][3]);
                A2[kt][2] = f16x2_of(D1[2 * kt + 1][0], D1[2 * kt + 1][1]);
                A2[kt][3] = f16x2_of(D1[2 * kt + 1][2], D1[2 * kt + 1][3]);
            }
        }

        // ---- layer-2 MMA: term-major per kt, 8 independent chains ----
        float D2[8][4];
        #pragma unroll
        for (int n = 0; n < 8; n++)
            #pragma unroll
            for (int c = 0; c < 4; c++) D2[n][c] = 0.0f;

        #pragma unroll
        for (int kt = 0; kt < 4; kt++) {
            uint32_t bh[4][4];
            #pragma unroll
            for (int p = 0; p < 4; p++) {
                const uint32_t roff = ((2 * p + ntoff) * 8 + local) * BSTR + kt * 32 + kc * 16;
                ldsm_x4(bh[p], sb + OFF_B2H + roff);
            }
            #pragma unroll
            for (int p = 0; p < 4; p++) {
                mma_f16(D2[2 * p],     A2[kt], &bh[p][0]);
                mma_f16(D2[2 * p + 1], A2[kt], &bh[p][2]);
            }
        }

        // ---- epilogue-2: relu + b2, dot with Wp, quad-reduce, store ----
        {
            float p0 = 0.0f, p1 = 0.0f;
            #pragma unroll
            for (int n = 0; n < 8; n++) {
                const float2 g  = *(const float2*)(base + OFF_B2 + (n * 8 + 2 * q) * 4);
                const float2 wv = *(const float2*)(base + OFF_WP + (n * 8 + 2 * q) * 4);
                p0 = fmaf(wv.x, fmaxf(D2[n][0] + g.x, 0.0f), p0);
                p0 = fmaf(wv.y, fmaxf(D2[n][1] + g.y, 0.0f), p0);
                p1 = fmaf(wv.x, fmaxf(D2[n][2] + g.x, 0.0f), p1);
                p1 = fmaf(wv.y, fmaxf(D2[n][3] + g.y, 0.0f), p1);
            }
            p0 += __shfl_xor_sync(0xffffffffu, p0, 1);
            p0 += __shfl_xor_sync(0xffffffffu, p0, 2);
            p1 += __shfl_xor_sync(0xffffffffu, p1, 1);
            p1 += __shfl_xor_sync(0xffffffffu, p1, 2);
            if (q == 0) {
                const int n0 = mbase + r4;
                if (n0 < NN)     out[n0]     = p0 + bps;
                if (n0 + 8 < NN) out[n0 + 8] = p1 + bps;
            }
        }
    }
}

extern "C" void kernel_launch(void* const* d_in, const int* in_sizes, int n_in,
                              void* d_out, int out_size)
{
    const float* sf = (const float*)d_in[2];
    const float* W1 = (const float*)d_in[9];
    const float* b1 = (const float*)d_in[10];
    const float* W2 = (const float*)d_in[11];
    const float* b2 = (const float*)d_in[12];
    const float* Wp = (const float*)d_in[13];
    const float* bp = (const float*)d_in[14];
    float* out = (float*)d_out;

    cudaFuncSetAttribute(fused_mlp_hmma7,
                         cudaFuncAttributeMaxDynamicSharedMemorySize, SMEM_DYN);
    fused_mlp_hmma7<<<GRID, TPB, SMEM_DYN>>>(sf, W1, b1, W2, b2, Wp, bp, out);
}